// round 13
// baseline (speedup 1.0000x reference)
#include <cuda_runtime.h>
#include <cuda_fp16.h>
#include <cstdint>
#include <cstddef>

// ---------------- problem constants ----------------
#define C_INC   128
#define C_OUTC  256
#define HDIM    64
#define WDIM    64
#define BSZ     16
#define KKC     1152          // C_IN * 9
#define M_TOT   65536
#define L_IMG   4096

// ---------------- fused GEMM tiling ----------------
#define BM   128              // 2 image rows
#define BN   128
#define NCHK 16               // chunks of 8 channels = 72 k-values (no pad)
#define AROW 160              // smem row stride bytes (144 data + 16 spacing)
#define B_STG (128 * AROW)    // 20480
#define X_STG (8 * 4 * 256)   // 8192
#define A_OFF (3 * B_STG)             // 61440
#define X_OFF (A_OFF + 128 * AROW)    // 81920
#define Q_OFF (X_OFF + 3 * X_STG)     // 106496
#define GEMM_SMEM (Q_OFF + KKC * 4)   // 111104  (occ 2)

// ---------------- device scratch ----------------
__device__ float g_wscale[KKC];
__device__ float g_apart[KKC * BSZ];  // per-(j, b) activation partial max
__device__ float g_scale[KKC];
__device__ float g_qfx[KKC];
__device__ float g_sx;
__device__ float g_sw;
__device__ __align__(16) __half g_wq_h[C_OUTC * KKC];

// ---------------- K1: activation partial max + weight max (fused) ----------
__global__ void k_prep(const float* __restrict__ x, const float* __restrict__ w) {
    int c = blockIdx.x, b = blockIdx.y;

    if (c >= C_INC) {                  // weight-max blocks (b == 0 only)
        if (b != 0) return;
        int j = (c - C_INC) * 256 + threadIdx.x;
        if (j >= KKC) return;
        float m = 0.f;
        for (int o = 0; o < C_OUTC; ++o)
            m = fmaxf(m, fabsf(w[o * KKC + j]));
        g_wscale[j] = m;
        return;
    }

    float m[9];
#pragma unroll
    for (int v = 0; v < 9; ++v) m[v] = 0.f;

    const float* xb = x + (((size_t)b * C_INC + c) << 12);
    for (int p = threadIdx.x; p < L_IMG; p += 256) {
        int h = p >> 6, ww = p & 63;
        float a = fabsf(xb[p]);
        bool h0 = (h < HDIM - 1);
        bool h2 = (h > 0);
        bool w0 = (ww < WDIM - 1);
        bool w2 = (ww > 0);
        if (h0 && w0) m[0] = fmaxf(m[0], a);
        if (h0)       m[1] = fmaxf(m[1], a);
        if (h0 && w2) m[2] = fmaxf(m[2], a);
        if (w0)       m[3] = fmaxf(m[3], a);
        m[4] = fmaxf(m[4], a);
        if (w2)       m[5] = fmaxf(m[5], a);
        if (h2 && w0) m[6] = fmaxf(m[6], a);
        if (h2)       m[7] = fmaxf(m[7], a);
        if (h2 && w2) m[8] = fmaxf(m[8], a);
    }

    __shared__ float sm[256];
    for (int v = 0; v < 9; ++v) {
        sm[threadIdx.x] = m[v];
        __syncthreads();
        for (int s = 128; s > 0; s >>= 1) {
            if (threadIdx.x < s)
                sm[threadIdx.x] = fmaxf(sm[threadIdx.x], sm[threadIdx.x + s]);
            __syncthreads();
        }
        if (threadIdx.x == 0)
            g_apart[(c * 9 + v) * BSZ + b] = sm[0];
        __syncthreads();
    }
}

// ---------------- K2: smooth scales + per-tensor quant scales ---------------
__global__ void k_scale() {
    __shared__ float red[256];
    __shared__ float s_sx_sh;
    int tid = threadIdx.x;

    float mx = 0.f, mw = 0.f;
    for (int j = tid; j < KKC; j += 256) {
        float a = 0.f;
#pragma unroll
        for (int b = 0; b < BSZ; ++b)
            a = fmaxf(a, g_apart[j * BSZ + b]);
        float w = g_wscale[j];
        float s = __fdiv_rn(__fsqrt_rn(a), __fsqrt_rn(w));
        if (s == 0.f) s = 1.f;
        g_scale[j] = s;
        mx = fmaxf(mx, __fdiv_rn(a, s));
        mw = fmaxf(mw, w * s);
    }

    red[tid] = mx; __syncthreads();
    for (int s = 128; s > 0; s >>= 1) {
        if (tid < s) red[tid] = fmaxf(red[tid], red[tid + s]);
        __syncthreads();
    }
    if (tid == 0) {
        float sx = __fdiv_rn(red[0], 127.f);
        if (sx == 0.f) sx = 1.f;
        g_sx = sx; s_sx_sh = sx;
    }
    __syncthreads();

    red[tid] = mw; __syncthreads();
    for (int s = 128; s > 0; s >>= 1) {
        if (tid < s) red[tid] = fmaxf(red[tid], red[tid + s]);
        __syncthreads();
    }
    if (tid == 0) {
        float sw = __fdiv_rn(red[0], 127.f);
        if (sw == 0.f) sw = 1.f;
        g_sw = sw;
    }
    __syncthreads();

    float sx = s_sx_sh;
    for (int j = tid; j < KKC; j += 256)
        g_qfx[j] = __fdiv_rn(1.f, g_scale[j] * sx);
}

// ---------------- K3: quantize weights -> fp16 ------------------------------
__global__ void k_wq(const float* __restrict__ w) {
    int i = blockIdx.x * blockDim.x + threadIdx.x;
    if (i >= C_OUTC * KKC) return;
    int j = i % KKC;
    float t = w[i] * g_scale[j];
    float q = rintf(__fdiv_rn(t, g_sw));
    q = fminf(fmaxf(q, -127.f), 127.f);
    g_wq_h[i] = __float2half_rn(q);
}

// ---------------- helpers ----------------------------------------------------
__device__ __forceinline__ void cp16(void* smem_dst, const void* gmem_src) {
    unsigned s = (unsigned)__cvta_generic_to_shared(smem_dst);
    asm volatile("cp.async.cg.shared.global [%0], [%1], 16;\n"
                 :: "r"(s), "l"(gmem_src));
}
__device__ __forceinline__ void cp16z(void* smem_dst, const void* gmem_src, int sz) {
    unsigned s = (unsigned)__cvta_generic_to_shared(smem_dst);
    asm volatile("cp.async.cg.shared.global [%0], [%1], 16, %2;\n"
                 :: "r"(s), "l"(gmem_src), "r"(sz));
}
__device__ __forceinline__ void ldsm4(uint32_t* r, const void* p) {
    unsigned a = (unsigned)__cvta_generic_to_shared(p);
    asm volatile("ldmatrix.sync.aligned.m8n8.x4.shared.b16 {%0,%1,%2,%3}, [%4];"
                 : "=r"(r[0]), "=r"(r[1]), "=r"(r[2]), "=r"(r[3]) : "r"(a));
}
__device__ __forceinline__ void mma_f16v(float* c, const uint32_t* a,
                                         uint32_t b0, uint32_t b1) {
    asm volatile(
        "mma.sync.aligned.m16n8k16.row.col.f32.f16.f16.f32 "
        "{%0,%1,%2,%3}, {%4,%5,%6,%7}, {%8,%9}, {%0,%1,%2,%3};\n"
        : "+f"(c[0]), "+f"(c[1]), "+f"(c[2]), "+f"(c[3])
        : "r"(a[0]), "r"(a[1]), "r"(a[2]), "r"(a[3]), "r"(b0), "r"(b1));
}
__device__ __forceinline__ void mma_f16k8(float* c, uint32_t a0, uint32_t a1,
                                          uint32_t b0) {
    asm volatile(
        "mma.sync.aligned.m16n8k8.row.col.f32.f16.f16.f32 "
        "{%0,%1,%2,%3}, {%4,%5}, {%6}, {%0,%1,%2,%3};\n"
        : "+f"(c[0]), "+f"(c[1]), "+f"(c[2]), "+f"(c[3])
        : "r"(a0), "r"(a1), "r"(b0));
}

// ---------------- K4: FUSED im2col + quantize + fp16 HMMA GEMM --------------
__global__ void __launch_bounds__(256, 2) k_gemm_f(const float* __restrict__ x,
                                                   const float* __restrict__ bias,
                                                   float* __restrict__ out) {
    extern __shared__ __align__(16) char smem[];

    int tid = threadIdx.x;
    int warpId = tid >> 5, lane = tid & 31;
    int wm = warpId & 1, wn = warpId >> 1;     // 2(m) x 4(n); warp tile 64x32
    int n0 = blockIdx.x * BN;
    size_t m0 = (size_t)blockIdx.y * BM;
    int b  = (int)(m0 >> 12);
    int h0 = (int)((m0 & 4095) >> 6);          // first of 2 image rows

    // conversion thread mapping
    int p    = tid & 127;                      // position within tile
    int grpC = tid >> 7;                       // channel half (0/1)
    int hl   = p >> 6, w = p & 63;

    float acc[4][4][4];
#pragma unroll
    for (int i = 0; i < 4; ++i)
#pragma unroll
        for (int j = 0; j < 4; ++j)
#pragma unroll
            for (int r = 0; r < 4; ++r) acc[i][j][r] = 0.f;

    const char* Bg = (const char*)g_wq_h;      // row stride 2304 B
    const float* xb = x + ((size_t)b * C_INC << 12);
    float* qfx_s = (float*)(smem + Q_OFF);

    // one-time qfx preload (used after first __syncthreads)
    for (int j = tid; j < KKC; j += 256) qfx_s[j] = __ldg(&g_qfx[j]);

    auto load_chunk = [&](int kt, int st) {
        char* Bs = smem + st * B_STG;
        char* Xs = smem + X_OFF + st * X_STG;
        // B: 128 rows x 144 B = 1152 granules
        for (int f = tid; f < 1152; f += 256) {
            int row = f / 9, g = f - row * 9;
            cp16(Bs + row * AROW + g * 16,
                 Bg + (size_t)(n0 + row) * 2304 + kt * 144 + g * 16);
        }
        // x strip: 8 ch x 4 rows x 256 B = 512 granules (zfill out-of-image)
        int c0 = kt * 8;
        for (int f = tid; f < 512; f += 256) {
            int ci = f >> 6, r = (f >> 4) & 3, g = f & 15;
            int hh = h0 - 1 + r;
            int ok = ((unsigned)hh < 64u);
            int hc = ok ? hh : 0;
            const char* src =
                (const char*)(xb + (((size_t)(c0 + ci)) << 12) + (hc << 6)) + g * 16;
            cp16z(Xs + (ci * 4 + r) * 256 + g * 16, src, ok ? 16 : 0);
        }
        asm volatile("cp.async.commit_group;\n" ::: "memory");
    };

    load_chunk(0, 0);
    load_chunk(1, 1);

    int lrow = lane & 15;
    int lcol = (lane >> 4) * 16;

    for (int kt = 0; kt < NCHK; ++kt) {
        if (kt + 1 < NCHK) {
            asm volatile("cp.async.wait_group 1;\n" ::: "memory");
        } else {
            asm volatile("cp.async.wait_group 0;\n" ::: "memory");
        }
        __syncthreads();   // chunk kt ready; prior MMA (A + stage reuse) done

        // ---- convert: x strip -> quantized fp16 A tile (128 x 72) ----
        {
            const float* Xf = (const float*)(smem + X_OFF + (kt % 3) * X_STG);
            const float* Qf = qfx_s + kt * 72;
            __half* Ar = (__half*)(smem + A_OFF + p * AROW);
#pragma unroll
            for (int pr = 0; pr < 2; ++pr) {          // channel pairs
                float q[18];
#pragma unroll
                for (int cc = 0; cc < 2; ++cc) {
                    int ci = grpC * 4 + pr * 2 + cc;
#pragma unroll
                    for (int kh = 0; kh < 3; ++kh) {
                        const float* xr = Xf + (ci * 4 + hl + kh) * 64;
                        float fa = (w > 0)  ? xr[w - 1] : 0.f;
                        float fb = xr[w];
                        float fc = (w < 63) ? xr[w + 1] : 0.f;
                        int e = cc * 9 + kh * 3;
                        // clamp provably unnecessary: |v*qfx| <= 127*(1+4eps)
                        q[e]     = rintf(fa * Qf[ci * 9 + kh * 3 + 0]);
                        q[e + 1] = rintf(fb * Qf[ci * 9 + kh * 3 + 1]);
                        q[e + 2] = rintf(fc * Qf[ci * 9 + kh * 3 + 2]);
                    }
                }
                __half2* dst = (__half2*)(Ar + (grpC * 4 + pr * 2) * 9);
#pragma unroll
                for (int t = 0; t < 9; ++t)
                    dst[t] = __floats2half2_rn(q[2 * t], q[2 * t + 1]);
            }
        }
        __syncthreads();   // A tile ready; x stage consumed

        if (kt + 2 < NCHK) load_chunk(kt + 2, (kt + 2) % 3);

        const char* Ab = smem + A_OFF;
        const char* Bb = smem + (kt % 3) * B_STG;

        // ---- 4 x k16 MMA steps (k 0..63) ----
#pragma unroll
        for (int ks = 0; ks < 4; ++ks) {
            uint32_t af[4][4], bf[2][4];
#pragma unroll
            for (int i = 0; i < 4; ++i)
                ldsm4(af[i], Ab + (wm * 64 + i * 16 + lrow) * AROW + ks * 32 + lcol);
#pragma unroll
            for (int j2 = 0; j2 < 2; ++j2)
                ldsm4(bf[j2], Bb + (wn * 32 + j2 * 16 + lrow) * AROW + ks * 32 + lcol);
#pragma unroll
            for (int i = 0; i < 4; ++i)
#pragma unroll
                for (int j = 0; j < 4; ++j) {
                    int j2 = j >> 1, hi = j & 1;
                    mma_f16v(acc[i][j], af[i],
                             hi ? bf[j2][1] : bf[j2][0],
                             hi ? bf[j2][3] : bf[j2][2]);
                }
        }

        // ---- final k8 step (k 64..71) ----
        {
            uint32_t a8[2][4], b8[4];
            ldsm4(a8[0], Ab + (wm * 64 + lane) * AROW + 128);        // rows 0-31
            ldsm4(a8[1], Ab + (wm * 64 + 32 + lane) * AROW + 128);   // rows 32-63
            ldsm4(b8,    Bb + (wn * 32 + lane) * AROW + 128);        // n 0-31
#pragma unroll
            for (int i = 0; i < 4; ++i) {
                uint32_t a0 = a8[i >> 1][(i & 1) * 2];
                uint32_t a1 = a8[i >> 1][(i & 1) * 2 + 1];
#pragma unroll
                for (int j = 0; j < 4; ++j)
                    mma_f16k8(acc[i][j], a0, a1, b8[j]);
            }
        }
    }

    // ---- epilogue: smem transpose (stride 129) -> float4 NCHW stores -------
    float* sbuf = (float*)smem;              // 128 x 129 floats = 66048 B
    int grp = lane >> 2, tig = lane & 3;
    __syncthreads();
#pragma unroll
    for (int i = 0; i < 4; ++i)
#pragma unroll
        for (int j = 0; j < 4; ++j)
#pragma unroll
            for (int r = 0; r < 4; ++r) {
                int m = wm * 64 + i * 16 + grp + (r >> 1) * 8;
                int n = wn * 32 + j * 8 + tig * 2 + (r & 1);
                sbuf[m * 129 + n] = acc[i][j][r];
            }
    __syncthreads();

    float osc = g_sx * g_sw;
    int p0 = (int)(m0 & 4095);
    int og = tid >> 5;                       // 8 channel groups
    int mv = lane * 4;
#pragma unroll
    for (int rep = 0; rep < 16; ++rep) {
        int nl = og + rep * 8;
        int o  = n0 + nl;
        float bz = __ldg(&bias[o]);
        float4 v;
        v.x = sbuf[(mv + 0) * 129 + nl] * osc + bz;
        v.y = sbuf[(mv + 1) * 129 + nl] * osc + bz;
        v.z = sbuf[(mv + 2) * 129 + nl] * osc + bz;
        v.w = sbuf[(mv + 3) * 129 + nl] * osc + bz;
        *(float4*)(out + (((size_t)b * C_OUTC + o) << 12) + p0 + mv) = v;
    }
}

// ---------------- launch -----------------------------------------------------
extern "C" void kernel_launch(void* const* d_in, const int* in_sizes, int n_in,
                              void* d_out, int out_size) {
    const float* x    = (const float*)d_in[0];
    const float* wt   = (const float*)d_in[1];
    const float* bias = (const float*)d_in[2];
    float* out = (float*)d_out;

    cudaFuncSetAttribute(k_gemm_f, cudaFuncAttributeMaxDynamicSharedMemorySize,
                         GEMM_SMEM);

    k_prep<<<dim3(C_INC + 5, BSZ), 256>>>(x, wt);
    k_scale<<<1, 256>>>();
    k_wq<<<(C_OUTC * KKC) / 256, 256>>>(wt);
    k_gemm_f<<<dim3(C_OUTC / BN, M_TOT / BM), 256, GEMM_SMEM>>>(x, bias, out);
}

// round 14
// speedup vs baseline: 1.8481x; 1.8481x over previous
#include <cuda_runtime.h>
#include <cuda_fp16.h>
#include <cstdint>
#include <cstddef>

// ---------------- problem constants ----------------
#define C_INC   128
#define C_OUTC  256
#define HDIM    64
#define WDIM    64
#define BSZ     16
#define KKC     1152          // C_IN * 9
#define M_TOT   65536
#define L_IMG   4096

// ---------------- fused GEMM tiling ----------------
#define BM   128              // 2 image rows
#define BN   128
#define NCHK 16               // chunks of 8 channels = 72 k-values (no pad)
#define AROW 176              // smem row stride (144 data + 32 pad) -> 12r mod 32 banks, conflict-free
#define B_STG (128 * AROW)    // 22528
#define X_STG (8 * 4 * 256)   // 8192
#define A_OFF (3 * B_STG)             // 67584
#define X_OFF (A_OFF + 128 * AROW)    // 90112
#define Q_OFF (X_OFF + 3 * X_STG)     // 114688
#define GEMM_SMEM (Q_OFF + 3 * 288)   // 115552  (<= 116736 for occupancy 2)

// ---------------- device scratch ----------------
__device__ float g_wscale[KKC];
__device__ float g_apart[KKC * BSZ];  // per-(j, b) activation partial max
__device__ float g_scale[KKC];
__device__ float g_qfx[KKC];
__device__ float g_sx;
__device__ float g_sw;
__device__ __align__(16) __half g_wq_h[C_OUTC * KKC];

// ---------------- K1: activation partial max + weight max (fused) ----------
__global__ void k_prep(const float* __restrict__ x, const float* __restrict__ w) {
    int c = blockIdx.x, b = blockIdx.y;

    if (c >= C_INC) {                  // weight-max blocks (b == 0 only)
        if (b != 0) return;
        int j = (c - C_INC) * 256 + threadIdx.x;
        if (j >= KKC) return;
        float m = 0.f;
        for (int o = 0; o < C_OUTC; ++o)
            m = fmaxf(m, fabsf(w[o * KKC + j]));
        g_wscale[j] = m;
        return;
    }

    float m[9];
#pragma unroll
    for (int v = 0; v < 9; ++v) m[v] = 0.f;

    const float* xb = x + (((size_t)b * C_INC + c) << 12);
    for (int p = threadIdx.x; p < L_IMG; p += 256) {
        int h = p >> 6, ww = p & 63;
        float a = fabsf(xb[p]);
        bool h0 = (h < HDIM - 1);
        bool h2 = (h > 0);
        bool w0 = (ww < WDIM - 1);
        bool w2 = (ww > 0);
        if (h0 && w0) m[0] = fmaxf(m[0], a);
        if (h0)       m[1] = fmaxf(m[1], a);
        if (h0 && w2) m[2] = fmaxf(m[2], a);
        if (w0)       m[3] = fmaxf(m[3], a);
        m[4] = fmaxf(m[4], a);
        if (w2)       m[5] = fmaxf(m[5], a);
        if (h2 && w0) m[6] = fmaxf(m[6], a);
        if (h2)       m[7] = fmaxf(m[7], a);
        if (h2 && w2) m[8] = fmaxf(m[8], a);
    }

    __shared__ float sm[256];
    for (int v = 0; v < 9; ++v) {
        sm[threadIdx.x] = m[v];
        __syncthreads();
        for (int s = 128; s > 0; s >>= 1) {
            if (threadIdx.x < s)
                sm[threadIdx.x] = fmaxf(sm[threadIdx.x], sm[threadIdx.x + s]);
            __syncthreads();
        }
        if (threadIdx.x == 0)
            g_apart[(c * 9 + v) * BSZ + b] = sm[0];
        __syncthreads();
    }
}

// ---------------- K2: smooth scales + per-tensor quant scales ---------------
__global__ void k_scale() {
    __shared__ float red[256];
    __shared__ float s_sx_sh;
    int tid = threadIdx.x;

    float mx = 0.f, mw = 0.f;
    for (int j = tid; j < KKC; j += 256) {
        float a = 0.f;
#pragma unroll
        for (int b = 0; b < BSZ; ++b)
            a = fmaxf(a, g_apart[j * BSZ + b]);
        float w = g_wscale[j];
        float s = __fdiv_rn(__fsqrt_rn(a), __fsqrt_rn(w));
        if (s == 0.f) s = 1.f;
        g_scale[j] = s;
        mx = fmaxf(mx, __fdiv_rn(a, s));
        mw = fmaxf(mw, w * s);
    }

    red[tid] = mx; __syncthreads();
    for (int s = 128; s > 0; s >>= 1) {
        if (tid < s) red[tid] = fmaxf(red[tid], red[tid + s]);
        __syncthreads();
    }
    if (tid == 0) {
        float sx = __fdiv_rn(red[0], 127.f);
        if (sx == 0.f) sx = 1.f;
        g_sx = sx; s_sx_sh = sx;
    }
    __syncthreads();

    red[tid] = mw; __syncthreads();
    for (int s = 128; s > 0; s >>= 1) {
        if (tid < s) red[tid] = fmaxf(red[tid], red[tid + s]);
        __syncthreads();
    }
    if (tid == 0) {
        float sw = __fdiv_rn(red[0], 127.f);
        if (sw == 0.f) sw = 1.f;
        g_sw = sw;
    }
    __syncthreads();

    float sx = s_sx_sh;
    for (int j = tid; j < KKC; j += 256)
        g_qfx[j] = __fdiv_rn(1.f, g_scale[j] * sx);
}

// ---------------- K3: quantize weights -> fp16 ------------------------------
__global__ void k_wq(const float* __restrict__ w) {
    int i = blockIdx.x * blockDim.x + threadIdx.x;
    if (i >= C_OUTC * KKC) return;
    int j = i % KKC;
    float t = w[i] * g_scale[j];
    float q = rintf(__fdiv_rn(t, g_sw));
    q = fminf(fmaxf(q, -127.f), 127.f);
    g_wq_h[i] = __float2half_rn(q);
}

// ---------------- helpers ----------------------------------------------------
__device__ __forceinline__ void cp16(void* smem_dst, const void* gmem_src) {
    unsigned s = (unsigned)__cvta_generic_to_shared(smem_dst);
    asm volatile("cp.async.cg.shared.global [%0], [%1], 16;\n"
                 :: "r"(s), "l"(gmem_src));
}
__device__ __forceinline__ void cp16z(void* smem_dst, const void* gmem_src, int sz) {
    unsigned s = (unsigned)__cvta_generic_to_shared(smem_dst);
    asm volatile("cp.async.cg.shared.global [%0], [%1], 16, %2;\n"
                 :: "r"(s), "l"(gmem_src), "r"(sz));
}
__device__ __forceinline__ void ldsm4(uint32_t* r, const void* p) {
    unsigned a = (unsigned)__cvta_generic_to_shared(p);
    asm volatile("ldmatrix.sync.aligned.m8n8.x4.shared.b16 {%0,%1,%2,%3}, [%4];"
                 : "=r"(r[0]), "=r"(r[1]), "=r"(r[2]), "=r"(r[3]) : "r"(a));
}
__device__ __forceinline__ void mma_f16v(float* c, const uint32_t* a,
                                         uint32_t b0, uint32_t b1) {
    asm volatile(
        "mma.sync.aligned.m16n8k16.row.col.f32.f16.f16.f32 "
        "{%0,%1,%2,%3}, {%4,%5,%6,%7}, {%8,%9}, {%0,%1,%2,%3};\n"
        : "+f"(c[0]), "+f"(c[1]), "+f"(c[2]), "+f"(c[3])
        : "r"(a[0]), "r"(a[1]), "r"(a[2]), "r"(a[3]), "r"(b0), "r"(b1));
}
__device__ __forceinline__ void mma_f16k8(float* c, uint32_t a0, uint32_t a1,
                                          uint32_t b0) {
    asm volatile(
        "mma.sync.aligned.m16n8k8.row.col.f32.f16.f16.f32 "
        "{%0,%1,%2,%3}, {%4,%5}, {%6}, {%0,%1,%2,%3};\n"
        : "+f"(c[0]), "+f"(c[1]), "+f"(c[2]), "+f"(c[3])
        : "r"(a0), "r"(a1), "r"(b0));
}

// ---------------- K4: FUSED im2col + quantize + fp16 HMMA GEMM --------------
__global__ void __launch_bounds__(256, 2) k_gemm_f(const float* __restrict__ x,
                                                   const float* __restrict__ bias,
                                                   float* __restrict__ out) {
    extern __shared__ __align__(16) char smem[];

    int tid = threadIdx.x;
    int warpId = tid >> 5, lane = tid & 31;
    int wm = warpId & 1, wn = warpId >> 1;     // 2(m) x 4(n); warp tile 64x32
    int n0 = blockIdx.x * BN;
    size_t m0 = (size_t)blockIdx.y * BM;
    int b  = (int)(m0 >> 12);
    int h0 = (int)((m0 & 4095) >> 6);          // first of 2 image rows

    // conversion thread mapping
    int p    = tid & 127;                      // position within tile
    int grpC = tid >> 7;                       // channel half (0/1)
    int hl   = p >> 6, w = p & 63;

    float acc[4][4][4];
#pragma unroll
    for (int i = 0; i < 4; ++i)
#pragma unroll
        for (int j = 0; j < 4; ++j)
#pragma unroll
            for (int r = 0; r < 4; ++r) acc[i][j][r] = 0.f;

    const char* Bg = (const char*)g_wq_h;      // row stride 2304 B
    const float* xb = x + ((size_t)b * C_INC << 12);

    auto load_chunk = [&](int kt, int st) {
        char* Bs = smem + st * B_STG;
        char* Xs = smem + X_OFF + st * X_STG;
        char* Qs = smem + Q_OFF + st * 288;
        // B: 128 rows x 144 B = 1152 granules
        for (int f = tid; f < 1152; f += 256) {
            int row = f / 9, g = f - row * 9;
            cp16(Bs + row * AROW + g * 16,
                 Bg + (size_t)(n0 + row) * 2304 + kt * 144 + g * 16);
        }
        // x strip: 8 ch x 4 rows x 256 B = 512 granules (zfill out-of-image)
        int c0 = kt * 8;
        for (int f = tid; f < 512; f += 256) {
            int ci = f >> 6, r = (f >> 4) & 3, g = f & 15;
            int hh = h0 - 1 + r;
            int ok = ((unsigned)hh < 64u);
            int hc = ok ? hh : 0;
            const char* src =
                (const char*)(xb + (((size_t)(c0 + ci)) << 12) + (hc << 6)) + g * 16;
            cp16z(Xs + (ci * 4 + r) * 256 + g * 16, src, ok ? 16 : 0);
        }
        // qfx slice: 72 floats = 18 granules
        if (tid < 18)
            cp16(Qs + tid * 16, (const char*)g_qfx + kt * 288 + tid * 16);
        asm volatile("cp.async.commit_group;\n" ::: "memory");
    };

    load_chunk(0, 0);
    load_chunk(1, 1);

    int lrow = lane & 15;
    int lcol = (lane >> 4) * 16;

    for (int kt = 0; kt < NCHK; ++kt) {
        if (kt + 1 < NCHK) {
            asm volatile("cp.async.wait_group 1;\n" ::: "memory");
        } else {
            asm volatile("cp.async.wait_group 0;\n" ::: "memory");
        }
        __syncthreads();   // chunk kt ready; prior MMA (A + stage reuse) done

        // ---- convert: x strip -> quantized fp16 A tile (128 x 72) ----
        {
            int st = kt % 3;
            const float* Xf = (const float*)(smem + X_OFF + st * X_STG);
            const float* Qf = (const float*)(smem + Q_OFF + st * 288);
            __half* Ar = (__half*)(smem + A_OFF + p * AROW);
#pragma unroll
            for (int pr = 0; pr < 2; ++pr) {          // channel pairs
                float q[18];
#pragma unroll
                for (int cc = 0; cc < 2; ++cc) {
                    int ci = grpC * 4 + pr * 2 + cc;
#pragma unroll
                    for (int kh = 0; kh < 3; ++kh) {
                        const float* xr = Xf + (ci * 4 + hl + kh) * 64;
                        float fa = (w > 0)  ? xr[w - 1] : 0.f;
                        float fb = xr[w];
                        float fc = (w < 63) ? xr[w + 1] : 0.f;
                        int e = cc * 9 + kh * 3;
                        // clamp provably unnecessary: |v*qfx| <= 127*(1+4eps)
                        q[e]     = rintf(fa * Qf[ci * 9 + kh * 3 + 0]);
                        q[e + 1] = rintf(fb * Qf[ci * 9 + kh * 3 + 1]);
                        q[e + 2] = rintf(fc * Qf[ci * 9 + kh * 3 + 2]);
                    }
                }
                __half2* dst = (__half2*)(Ar + (grpC * 4 + pr * 2) * 9);
#pragma unroll
                for (int t = 0; t < 9; ++t)
                    dst[t] = __floats2half2_rn(q[2 * t], q[2 * t + 1]);
            }
        }
        __syncthreads();   // A tile ready; x stage consumed

        if (kt + 2 < NCHK) load_chunk(kt + 2, (kt + 2) % 3);

        const char* Ab = smem + A_OFF;
        const char* Bb = smem + (kt % 3) * B_STG;

        // ---- 4 x k16 MMA steps (k 0..63) ----
#pragma unroll
        for (int ks = 0; ks < 4; ++ks) {
            uint32_t af[4][4], bf[2][4];
#pragma unroll
            for (int i = 0; i < 4; ++i)
                ldsm4(af[i], Ab + (wm * 64 + i * 16 + lrow) * AROW + ks * 32 + lcol);
#pragma unroll
            for (int j2 = 0; j2 < 2; ++j2)
                ldsm4(bf[j2], Bb + (wn * 32 + j2 * 16 + lrow) * AROW + ks * 32 + lcol);
#pragma unroll
            for (int i = 0; i < 4; ++i)
#pragma unroll
                for (int j = 0; j < 4; ++j) {
                    int j2 = j >> 1, hi = j & 1;
                    mma_f16v(acc[i][j], af[i],
                             hi ? bf[j2][1] : bf[j2][0],
                             hi ? bf[j2][3] : bf[j2][2]);
                }
        }

        // ---- final k8 step (k 64..71) ----
        {
            uint32_t a8[2][4], b8[4];
            ldsm4(a8[0], Ab + (wm * 64 + lane) * AROW + 128);        // rows 0-31
            ldsm4(a8[1], Ab + (wm * 64 + 32 + lane) * AROW + 128);   // rows 32-63
            ldsm4(b8,    Bb + (wn * 32 + lane) * AROW + 128);        // n 0-31
#pragma unroll
            for (int i = 0; i < 4; ++i) {
                uint32_t a0 = a8[i >> 1][(i & 1) * 2];
                uint32_t a1 = a8[i >> 1][(i & 1) * 2 + 1];
#pragma unroll
                for (int j = 0; j < 4; ++j)
                    mma_f16k8(acc[i][j], a0, a1, b8[j]);
            }
        }
    }

    // ---- epilogue: smem transpose (stride 129) -> float4 NCHW stores -------
    float* sbuf = (float*)smem;              // 128 x 129 floats = 66048 B
    int grp = lane >> 2, tig = lane & 3;
    __syncthreads();
#pragma unroll
    for (int i = 0; i < 4; ++i)
#pragma unroll
        for (int j = 0; j < 4; ++j)
#pragma unroll
            for (int r = 0; r < 4; ++r) {
                int m = wm * 64 + i * 16 + grp + (r >> 1) * 8;
                int n = wn * 32 + j * 8 + tig * 2 + (r & 1);
                sbuf[m * 129 + n] = acc[i][j][r];
            }
    __syncthreads();

    float osc = g_sx * g_sw;
    int p0 = (int)(m0 & 4095);
    int og = tid >> 5;                       // 8 channel groups
    int mv = lane * 4;
#pragma unroll
    for (int rep = 0; rep < 16; ++rep) {
        int nl = og + rep * 8;
        int o  = n0 + nl;
        float bz = __ldg(&bias[o]);
        float4 v;
        v.x = sbuf[(mv + 0) * 129 + nl] * osc + bz;
        v.y = sbuf[(mv + 1) * 129 + nl] * osc + bz;
        v.z = sbuf[(mv + 2) * 129 + nl] * osc + bz;
        v.w = sbuf[(mv + 3) * 129 + nl] * osc + bz;
        *(float4*)(out + (((size_t)b * C_OUTC + o) << 12) + p0 + mv) = v;
    }
}

// ---------------- launch -----------------------------------------------------
extern "C" void kernel_launch(void* const* d_in, const int* in_sizes, int n_in,
                              void* d_out, int out_size) {
    const float* x    = (const float*)d_in[0];
    const float* wt   = (const float*)d_in[1];
    const float* bias = (const float*)d_in[2];
    float* out = (float*)d_out;

    cudaFuncSetAttribute(k_gemm_f, cudaFuncAttributeMaxDynamicSharedMemorySize,
                         GEMM_SMEM);

    k_prep<<<dim3(C_INC + 5, BSZ), 256>>>(x, wt);
    k_scale<<<1, 256>>>();
    k_wq<<<(C_OUTC * KKC) / 256, 256>>>(wt);
    k_gemm_f<<<dim3(C_OUTC / BN, M_TOT / BM), 256, GEMM_SMEM>>>(x, bias, out);
}